// round 11
// baseline (speedup 1.0000x reference)
#include <cuda_runtime.h>
#include <math.h>

#define NSNPS  500000
#define NGENES 20000
#define NNODES 600000
#define NEDGES 320000
#define NB     16
#define NF     8

#define SCAT_BLOCKS ((NEDGES + 255) / 256)   // 1250
#define PRE_BLOCKS  ((NSNPS + 255) / 256)    // 1954
#define GENE_BLOCKS (NGENES / 8)             // 2500 (8 genes/block, 1 warp/gene)

// rsqrt(1 + 1e-5)
#define BN_RS 0.9999950000374997f

// -------- scratch (static device allocations; zero-initialized at load) --------
__device__ float d_snpT[(size_t)NSNPS * NB];     // 32 MB  [snp][b]
__device__ float d_fT[(size_t)NSNPS * NF];       // 16 MB  [snp][f]
__device__ float d_hA[(size_t)NGENES * NB * NF]; // 10.24 MB [g][b][f]
__device__ float d_hB[(size_t)NGENES * NB * NF];
__device__ int   d_seg[NGENES + 1];
__device__ int   d_deg[NGENES];   // INVARIANT: zero on entry (k_scan_pre re-zeros)
__device__ int   d_cur[NGENES];
__device__ int   d_off[NGENES + 1];
__device__ int   d_csr[NEDGES];
__device__ float d_gh[NB * NF];   // INVARIANT: zero on entry (k_head re-zeros)

__device__ __forceinline__ float gelu_f(float x) { return x * normcdff(x); }

// -------- launch 1: edge-degree histogram + per-gene node-segment starts --------
__global__ void k_hist_seg(const int* __restrict__ dst, const int* __restrict__ gon) {
    int i = blockIdx.x * blockDim.x + threadIdx.x;
    if (i <= NGENES) {
        int lo = 0, hi = NNODES;
        while (lo < hi) {
            int mid = (lo + hi) >> 1;
            if (gon[mid] < i) lo = mid + 1; else hi = mid;
        }
        d_seg[i] = lo;
    }
    if (i < NEDGES) atomicAdd(&d_deg[dst[i]], 1);
}

// -------- launch 2: block 0 = exclusive scan (re-zero deg); blocks 1.. = transpose --------
__global__ void __launch_bounds__(256) k_scan_pre(
        const float* __restrict__ snp, const float* __restrict__ filters,
        float* __restrict__ outF) {
    if (blockIdx.x == 0) {
        __shared__ int sh[256];
        const int PER = (NGENES + 255) / 256;  // 79
        int tid = threadIdx.x;
        int base = tid * PER;
        int s = 0;
        for (int i = 0; i < PER; i++) {
            int idx = base + i;
            if (idx < NGENES) s += d_deg[idx];
        }
        sh[tid] = s;
        __syncthreads();
        for (int off = 1; off < 256; off <<= 1) {
            int add = 0;
            if (tid >= off) add = sh[tid - off];
            __syncthreads();
            sh[tid] += add;
            __syncthreads();
        }
        int run = (tid == 0) ? 0 : sh[tid - 1];
        for (int i = 0; i < PER; i++) {
            int idx = base + i;
            if (idx < NGENES) {
                d_off[idx] = run;
                d_cur[idx] = run;
                run += d_deg[idx];
                d_deg[idx] = 0;   // restore invariant for next graph replay
            }
        }
        if (tid == 255) d_off[NGENES] = run;
        return;
    }
    // transpose blocks
    __shared__ float smem_s[256][NB + 1];
    __shared__ float smem_f[256][NF + 1];
    int tid = threadIdx.x;
    int t = (blockIdx.x - 1) * 256 + tid;
    bool ok = (t < NSNPS);
#pragma unroll
    for (int b = 0; b < NB; b++)
        smem_s[tid][b] = ok ? snp[(size_t)b * NSNPS + t] : 0.f;
#pragma unroll
    for (int f = 0; f < NF; f++) {
        float w = ok ? filters[(size_t)f * NSNPS + t] : 0.f;
        smem_f[tid][f] = w;
        if (ok) outF[(size_t)f * NSNPS + t] = w;
    }
    __syncthreads();
    if (ok) {
        float4* dp = (float4*)&d_snpT[(size_t)t * NB];
        dp[0] = make_float4(smem_s[tid][0],  smem_s[tid][1],  smem_s[tid][2],  smem_s[tid][3]);
        dp[1] = make_float4(smem_s[tid][4],  smem_s[tid][5],  smem_s[tid][6],  smem_s[tid][7]);
        dp[2] = make_float4(smem_s[tid][8],  smem_s[tid][9],  smem_s[tid][10], smem_s[tid][11]);
        dp[3] = make_float4(smem_s[tid][12], smem_s[tid][13], smem_s[tid][14], smem_s[tid][15]);
        float4* fp = (float4*)&d_fT[(size_t)t * NF];
        fp[0] = make_float4(smem_f[tid][0], smem_f[tid][1], smem_f[tid][2], smem_f[tid][3]);
        fp[1] = make_float4(smem_f[tid][4], smem_f[tid][5], smem_f[tid][6], smem_f[tid][7]);
    }
}

// -------- launch 3: CSR scatter (blocks 0..1249) + SNP->gene readout (1250..3749) --------
// gene part: 1 warp per gene; lane = half*16 + b; half-warps take alternate nodes.
__global__ void __launch_bounds__(256) k_scatter_gene(
        const int* __restrict__ src, const int* __restrict__ dst,
        const int* __restrict__ snp_ids) {
    int tid = threadIdx.x;
    if (blockIdx.x < SCAT_BLOCKS) {
        int e = blockIdx.x * 256 + tid;
        if (e < NEDGES) {
            int p = atomicAdd(&d_cur[dst[e]], 1);
            d_csr[p] = src[e];
        }
        return;
    }
    int g = (blockIdx.x - SCAT_BLOCKS) * 8 + (tid >> 5);
    int lane = tid & 31;
    int half = lane >> 4, b = lane & 15;
    float a0x=0.f,a0y=0.f,a0z=0.f,a0w=0.f,a1x=0.f,a1y=0.f,a1z=0.f,a1w=0.f;
    int n0 = d_seg[g], n1 = d_seg[g + 1];
    int n = n0 + half;
    // unroll-2 over this half's nodes (stride 2): 4 nodes in flight per warp
    for (; n + 2 < n1; n += 4) {
        int i0 = snp_ids[n], i1 = snp_ids[n + 2];
        float s0 = d_snpT[(size_t)i0 * NB + b];
        float s1 = d_snpT[(size_t)i1 * NB + b];
        const float4* p0 = (const float4*)&d_fT[(size_t)i0 * NF];
        const float4* p1 = (const float4*)&d_fT[(size_t)i1 * NF];
        float4 f00 = p0[0], f01 = p0[1];
        float4 f10 = p1[0], f11 = p1[1];
        a0x += s0 * f00.x; a0y += s0 * f00.y; a0z += s0 * f00.z; a0w += s0 * f00.w;
        a1x += s0 * f01.x; a1y += s0 * f01.y; a1z += s0 * f01.z; a1w += s0 * f01.w;
        a0x += s1 * f10.x; a0y += s1 * f10.y; a0z += s1 * f10.z; a0w += s1 * f10.w;
        a1x += s1 * f11.x; a1y += s1 * f11.y; a1z += s1 * f11.z; a1w += s1 * f11.w;
    }
    for (; n < n1; n += 2) {
        int id = snp_ids[n];
        float sv = d_snpT[(size_t)id * NB + b];
        const float4* fp = (const float4*)&d_fT[(size_t)id * NF];
        float4 f0 = fp[0], f1 = fp[1];
        a0x += sv * f0.x; a0y += sv * f0.y; a0z += sv * f0.z; a0w += sv * f0.w;
        a1x += sv * f1.x; a1y += sv * f1.y; a1z += sv * f1.z; a1w += sv * f1.w;
    }
    // combine node-parity halves (partner = lane ^ 16)
    a0x += __shfl_xor_sync(0xffffffffu, a0x, 16);
    a0y += __shfl_xor_sync(0xffffffffu, a0y, 16);
    a0z += __shfl_xor_sync(0xffffffffu, a0z, 16);
    a0w += __shfl_xor_sync(0xffffffffu, a0w, 16);
    a1x += __shfl_xor_sync(0xffffffffu, a1x, 16);
    a1y += __shfl_xor_sync(0xffffffffu, a1y, 16);
    a1z += __shfl_xor_sync(0xffffffffu, a1z, 16);
    a1w += __shfl_xor_sync(0xffffffffu, a1w, 16);
    if (half == 0) {
        float4* hp = (float4*)&d_hA[((size_t)g * NB + b) * NF];
        hp[0] = make_float4(a0x, a0y, a0z, a0w);
        hp[1] = make_float4(a1x, a1y, a1z, a1w);
    }
}

// ======== cooperative layer core: 1 warp per gene, lane = b*2 + fhalf ========
// Lane owns float4 = elements [b*8 + fhalf*4 .. +3]. Partner = lane^1.
__device__ __forceinline__ float4 edge_agg32(const float* __restrict__ hin,
                                             int g, int lane, float ep) {
    const float4* h4in = (const float4*)hin;
    float4 a = h4in[(size_t)g * 32 + lane];
    a.x *= ep; a.y *= ep; a.z *= ep; a.w *= ep;
    int e0 = d_off[g], e1 = d_off[g + 1];
    int e = e0;
    for (; e + 4 <= e1; e += 4) {
        int s0 = d_csr[e], s1 = d_csr[e + 1], s2 = d_csr[e + 2], s3 = d_csr[e + 3];
        float4 x0 = h4in[(size_t)s0 * 32 + lane];
        float4 x1 = h4in[(size_t)s1 * 32 + lane];
        float4 x2 = h4in[(size_t)s2 * 32 + lane];
        float4 x3 = h4in[(size_t)s3 * 32 + lane];
        a.x += (x0.x + x1.x) + (x2.x + x3.x);
        a.y += (x0.y + x1.y) + (x2.y + x3.y);
        a.z += (x0.z + x1.z) + (x2.z + x3.z);
        a.w += (x0.w + x1.w) + (x2.w + x3.w);
    }
    for (; e < e1; e++) {
        float4 x = h4in[(size_t)d_csr[e] * 32 + lane];
        a.x += x.x; a.y += x.y; a.z += x.z; a.w += x.w;
    }
    return a;
}

// Cooperative MLP: in lane-float4 a (f-range h4..h4+3), out float4 o (same range).
__device__ __forceinline__ float4 gin_mlp32(float4 a, int h4,
                                            const float* sW1, const float* sB1,
                                            const float* sG1, const float* sT1,
                                            const float* sW2, const float* sB2,
                                            const float* sG2, const float* sT2) {
    float o0 = 0.f, o1 = 0.f, o2 = 0.f, o3 = 0.f;
#pragma unroll
    for (int j = 0; j < 16; j++) {
        float p = a.x * sW1[(h4 + 0) * 16 + j] + a.y * sW1[(h4 + 1) * 16 + j]
                + a.z * sW1[(h4 + 2) * 16 + j] + a.w * sW1[(h4 + 3) * 16 + j];
        p += __shfl_xor_sync(0xffffffffu, p, 1);
        float z = gelu_f((p + sB1[j]) * sG1[j] + sT1[j]);
        o0 += z * sW2[j * 8 + h4 + 0];
        o1 += z * sW2[j * 8 + h4 + 1];
        o2 += z * sW2[j * 8 + h4 + 2];
        o3 += z * sW2[j * 8 + h4 + 3];
    }
    float4 o;
    o.x = gelu_f((o0 + sB2[h4 + 0]) * sG2[h4 + 0] + sT2[h4 + 0]);
    o.y = gelu_f((o1 + sB2[h4 + 1]) * sG2[h4 + 1] + sT2[h4 + 1]);
    o.z = gelu_f((o2 + sB2[h4 + 2]) * sG2[h4 + 2] + sT2[h4 + 2]);
    o.w = gelu_f((o3 + sB2[h4 + 3]) * sG2[h4 + 3] + sT2[h4 + 3]);
    return o;
}

// -------- launch 4 (PROFILED): GIN layer 0: hA -> hB --------
__global__ void __launch_bounds__(256) k_layer0(
        const float* __restrict__ eps,
        const float* __restrict__ W1, const float* __restrict__ b1,
        const float* __restrict__ g1, const float* __restrict__ bt1,
        const float* __restrict__ W2, const float* __restrict__ b2,
        const float* __restrict__ g2, const float* __restrict__ bt2) {
    __shared__ float sW1[128], sW2[128], sB1[16], sG1[16], sT1[16], sB2[8], sG2[8], sT2[8];
    int tid = threadIdx.x;
    if (tid < 128) { sW1[tid] = W1[tid]; sW2[tid] = W2[tid]; }
    if (tid < 16) { sB1[tid] = b1[tid]; sG1[tid] = g1[tid] * BN_RS; sT1[tid] = bt1[tid]; }
    if (tid < 8)  { sB2[tid] = b2[tid]; sG2[tid] = g2[tid] * BN_RS; sT2[tid] = bt2[tid]; }
    __syncthreads();
    int g = blockIdx.x * 8 + (tid >> 5);
    int lane = tid & 31;
    int h4 = (lane & 1) * 4;
    float4 a = edge_agg32(d_hA, g, lane, 1.f + eps[0]);
    float4 o = gin_mlp32(a, h4, sW1, sB1, sG1, sT1, sW2, sB2, sG2, sT2);
    ((float4*)d_hB)[(size_t)g * 32 + lane] = o;
}

// -------- launch 5: GIN layer 1 fused with attentive readout --------
__global__ void __launch_bounds__(256) k_layer1_attn(
        const float* __restrict__ eps,
        const float* __restrict__ W1, const float* __restrict__ b1,
        const float* __restrict__ g1, const float* __restrict__ bt1,
        const float* __restrict__ W2, const float* __restrict__ b2,
        const float* __restrict__ g2, const float* __restrict__ bt2,
        const float* __restrict__ Wk, const float* __restrict__ bk,
        const float* __restrict__ Wq,
        const float* __restrict__ Wv, const float* __restrict__ bv,
        float* __restrict__ w_out) {
    __shared__ float sW1[128], sW2[128], sB1[16], sG1[16], sT1[16], sB2[8], sG2[8], sT2[8];
    __shared__ float sWk[64], sWv[64], sWq[8], sBk[8], sBv[8];
    __shared__ float red[8][16][8];  // [warp][b][f]
    int tid = threadIdx.x;
    if (tid < 128) { sW1[tid] = W1[128 + tid]; sW2[tid] = W2[128 + tid]; }
    if (tid < 16) { sB1[tid] = b1[16 + tid]; sG1[tid] = g1[16 + tid] * BN_RS; sT1[tid] = bt1[16 + tid]; }
    if (tid < 8)  { sB2[tid] = b2[8 + tid]; sG2[tid] = g2[8 + tid] * BN_RS; sT2[tid] = bt2[8 + tid]; }
    if (tid >= 128 && tid < 192) { sWk[tid - 128] = Wk[tid - 128]; sWv[tid - 128] = Wv[tid - 128]; }
    if (tid >= 192 && tid < 200) {
        int j = tid - 192;
        sWq[j] = Wq[j]; sBk[j] = bk[j]; sBv[j] = bv[j];
    }
    __syncthreads();

    int g = blockIdx.x * 8 + (tid >> 5);
    int lane = tid & 31;
    int fh = lane & 1, b = lane >> 1, h4 = fh * 4;
    float4 a = edge_agg32(d_hB, g, lane, 1.f + eps[1]);
    float4 o = gin_mlp32(a, h4, sW1, sB1, sG1, sT1, sW2, sB2, sG2, sT2);

    // attention: q = key(o) . Wq ; w = sigmoid(q) ; vw = value(o) * w
    float q = 0.f;
#pragma unroll
    for (int j = 0; j < 8; j++) {
        float p = o.x * sWk[(h4 + 0) * 8 + j] + o.y * sWk[(h4 + 1) * 8 + j]
                + o.z * sWk[(h4 + 2) * 8 + j] + o.w * sWk[(h4 + 3) * 8 + j];
        p += __shfl_xor_sync(0xffffffffu, p, 1);
        q += (p + sBk[j]) * sWq[j];
    }
    float wv = 1.f / (1.f + expf(-q));
    if (fh == 0) w_out[(size_t)b * NGENES + g] = wv;
    float vw[8];
#pragma unroll
    for (int j = 0; j < 8; j++) {
        float p = o.x * sWv[(h4 + 0) * 8 + j] + o.y * sWv[(h4 + 1) * 8 + j]
                + o.z * sWv[(h4 + 2) * 8 + j] + o.w * sWv[(h4 + 3) * 8 + j];
        p += __shfl_xor_sync(0xffffffffu, p, 1);
        vw[j] = (p + sBv[j]) * wv;
    }
    int wid = tid >> 5;
    if (fh == 0) {
#pragma unroll
        for (int j = 0; j < 8; j++) red[wid][b][j] = vw[j];
    }
    __syncthreads();
    if (tid < 128) {
        int bb = tid >> 3, f = tid & 7;
        float s = 0.f;
#pragma unroll
        for (int w = 0; w < 8; w++) s += red[w][bb][f];
        atomicAdd(&d_gh[bb * NF + f], s);
    }
}

// -------- launch 6: final MLP head: 8 -> 64 -> 16 -> 1; re-zero d_gh --------
__global__ void k_head(const float* __restrict__ Wp1, const float* __restrict__ bp1,
                       const float* __restrict__ gp1, const float* __restrict__ btp1,
                       const float* __restrict__ Wp2, const float* __restrict__ bp2,
                       const float* __restrict__ gp2, const float* __restrict__ btp2,
                       const float* __restrict__ Wp3, const float* __restrict__ bp3,
                       float* __restrict__ preds) {
    int b = threadIdx.x;
    if (b < NB) {
        float x[8];
#pragma unroll
        for (int f = 0; f < 8; f++) x[f] = d_gh[b * 8 + f];
        float z1[64];
        for (int j = 0; j < 64; j++) {
            float t = bp1[j];
#pragma unroll
            for (int f = 0; f < 8; f++) t += x[f] * Wp1[f * 64 + j];
            z1[j] = gelu_f(t * BN_RS * gp1[j] + btp1[j]);
        }
        float z2[16];
        for (int k = 0; k < 16; k++) {
            float t = bp2[k];
            for (int j = 0; j < 64; j++) t += z1[j] * Wp2[j * 16 + k];
            z2[k] = gelu_f(t * BN_RS * gp2[k] + btp2[k]);
        }
        float p = bp3[0];
#pragma unroll
        for (int k = 0; k < 16; k++) p += z2[k] * Wp3[k];
        preds[b] = p;
    }
    __syncthreads();
    for (int i = threadIdx.x; i < NB * NF; i += 32) d_gh[i] = 0.f;
}

extern "C" void kernel_launch(void* const* d_in, const int* in_sizes, int n_in,
                              void* d_out, int out_size) {
    const float* snp     = (const float*)d_in[0];
    const int*   snp_ids = (const int*)d_in[1];
    const int*   gon     = (const int*)d_in[2];
    const int*   esrc    = (const int*)d_in[3];
    const int*   edst    = (const int*)d_in[4];
    const float* filters = (const float*)d_in[5];
    const float* eps     = (const float*)d_in[6];
    const float* W1  = (const float*)d_in[7];
    const float* b1  = (const float*)d_in[8];
    const float* g1  = (const float*)d_in[9];
    const float* bt1 = (const float*)d_in[10];
    const float* W2  = (const float*)d_in[11];
    const float* b2  = (const float*)d_in[12];
    const float* g2  = (const float*)d_in[13];
    const float* bt2 = (const float*)d_in[14];
    const float* Wk  = (const float*)d_in[15];
    const float* bk  = (const float*)d_in[16];
    const float* Wq  = (const float*)d_in[17];
    const float* Wv  = (const float*)d_in[18];
    const float* bv  = (const float*)d_in[19];
    const float* Wp1 = (const float*)d_in[20];
    const float* bp1 = (const float*)d_in[21];
    const float* gp1 = (const float*)d_in[22];
    const float* btp1= (const float*)d_in[23];
    const float* Wp2 = (const float*)d_in[24];
    const float* bp2 = (const float*)d_in[25];
    const float* gp2 = (const float*)d_in[26];
    const float* btp2= (const float*)d_in[27];
    const float* Wp3 = (const float*)d_in[28];
    const float* bp3 = (const float*)d_in[29];

    float* out   = (float*)d_out;
    float* preds = out;                               // [16]
    float* outF  = out + NB;                          // [8*500000]
    float* w_out = out + NB + (size_t)NF * NSNPS;     // [16*20000]

    k_hist_seg<<<SCAT_BLOCKS, 256>>>(edst, gon);                                   // 1
    k_scan_pre<<<1 + PRE_BLOCKS, 256>>>(snp, filters, outF);                       // 2
    k_scatter_gene<<<SCAT_BLOCKS + GENE_BLOCKS, 256>>>(esrc, edst, snp_ids);       // 3
    k_layer0<<<GENE_BLOCKS, 256>>>(eps, W1, b1, g1, bt1, W2, b2, g2, bt2);         // 4 <- profiled
    k_layer1_attn<<<GENE_BLOCKS, 256>>>(eps, W1, b1, g1, bt1, W2, b2, g2, bt2,
                                        Wk, bk, Wq, Wv, bv, w_out);                // 5
    k_head<<<1, 32>>>(Wp1, bp1, gp1, btp1, Wp2, bp2, gp2, btp2, Wp3, bp3, preds);  // 6
}

// round 13
// speedup vs baseline: 1.1788x; 1.1788x over previous
#include <cuda_runtime.h>
#include <math.h>

#define NSNPS  500000
#define NGENES 20000
#define NNODES 600000
#define NEDGES 320000
#define NB     16
#define NF     8

#define SCAT_BLOCKS ((NEDGES + 255) / 256)   // 1250
#define PRE_BLOCKS  ((NSNPS + 255) / 256)    // 1954
#define GENE_BLOCKS (NGENES / 8)             // 2500 (8 genes/block, 1 warp/gene)

// rsqrt(1 + 1e-5)
#define BN_RS 0.9999950000374997f

// -------- scratch (static device allocations; zero-initialized at load) --------
__device__ float d_snpT[(size_t)NSNPS * NB];     // 32 MB  [snp][b]
__device__ float d_fT[(size_t)NSNPS * NF];       // 16 MB  [snp][f]
__device__ float d_hA[(size_t)NGENES * NB * NF]; // 10.24 MB [g][b][f]
__device__ float d_hB[(size_t)NGENES * NB * NF];
__device__ int   d_seg[NGENES + 1];
__device__ int   d_deg[NGENES];   // INVARIANT: zero on entry (k_scan_pre re-zeros)
__device__ int   d_cur[NGENES];
__device__ int   d_off[NGENES + 1];
__device__ int   d_csr[NEDGES];
__device__ float d_gh[NB * NF];   // INVARIANT: zero on entry (k_head re-zeros)

// fast exact-form GELU: erff is the fast polynomial path (vs normcdff -> erfcf slow path)
__device__ __forceinline__ float gelu_f(float x) {
    return 0.5f * x * (1.f + erff(x * 0.7071067811865475f));
}

// -------- launch 1: edge-degree histogram + per-gene node-segment starts --------
__global__ void k_hist_seg(const int* __restrict__ dst, const int* __restrict__ gon) {
    int i = blockIdx.x * blockDim.x + threadIdx.x;
    if (i <= NGENES) {
        int lo = 0, hi = NNODES;
        while (lo < hi) {
            int mid = (lo + hi) >> 1;
            if (gon[mid] < i) lo = mid + 1; else hi = mid;
        }
        d_seg[i] = lo;
    }
    if (i < NEDGES) atomicAdd(&d_deg[dst[i]], 1);
}

// -------- launch 2: block 0 = exclusive scan (re-zero deg); blocks 1.. = transpose --------
__global__ void __launch_bounds__(256) k_scan_pre(
        const float* __restrict__ snp, const float* __restrict__ filters,
        float* __restrict__ outF) {
    if (blockIdx.x == 0) {
        __shared__ int sh[256];
        const int PER = (NGENES + 255) / 256;  // 79
        int tid = threadIdx.x;
        int base = tid * PER;
        int s = 0;
        for (int i = 0; i < PER; i++) {
            int idx = base + i;
            if (idx < NGENES) s += d_deg[idx];
        }
        sh[tid] = s;
        __syncthreads();
        for (int off = 1; off < 256; off <<= 1) {
            int add = 0;
            if (tid >= off) add = sh[tid - off];
            __syncthreads();
            sh[tid] += add;
            __syncthreads();
        }
        int run = (tid == 0) ? 0 : sh[tid - 1];
        for (int i = 0; i < PER; i++) {
            int idx = base + i;
            if (idx < NGENES) {
                d_off[idx] = run;
                d_cur[idx] = run;
                run += d_deg[idx];
                d_deg[idx] = 0;   // restore invariant for next graph replay
            }
        }
        if (tid == 255) d_off[NGENES] = run;
        return;
    }
    // transpose blocks
    __shared__ float smem_s[256][NB + 1];
    __shared__ float smem_f[256][NF + 1];
    int tid = threadIdx.x;
    int t = (blockIdx.x - 1) * 256 + tid;
    bool ok = (t < NSNPS);
#pragma unroll
    for (int b = 0; b < NB; b++)
        smem_s[tid][b] = ok ? snp[(size_t)b * NSNPS + t] : 0.f;
#pragma unroll
    for (int f = 0; f < NF; f++) {
        float w = ok ? filters[(size_t)f * NSNPS + t] : 0.f;
        smem_f[tid][f] = w;
        if (ok) outF[(size_t)f * NSNPS + t] = w;
    }
    __syncthreads();
    if (ok) {
        float4* dp = (float4*)&d_snpT[(size_t)t * NB];
        dp[0] = make_float4(smem_s[tid][0],  smem_s[tid][1],  smem_s[tid][2],  smem_s[tid][3]);
        dp[1] = make_float4(smem_s[tid][4],  smem_s[tid][5],  smem_s[tid][6],  smem_s[tid][7]);
        dp[2] = make_float4(smem_s[tid][8],  smem_s[tid][9],  smem_s[tid][10], smem_s[tid][11]);
        dp[3] = make_float4(smem_s[tid][12], smem_s[tid][13], smem_s[tid][14], smem_s[tid][15]);
        float4* fp = (float4*)&d_fT[(size_t)t * NF];
        fp[0] = make_float4(smem_f[tid][0], smem_f[tid][1], smem_f[tid][2], smem_f[tid][3]);
        fp[1] = make_float4(smem_f[tid][4], smem_f[tid][5], smem_f[tid][6], smem_f[tid][7]);
    }
}

// -------- launch 3: CSR scatter (blocks 0..1249) + SNP->gene readout (1250..3749) --------
__global__ void __launch_bounds__(256) k_scatter_gene(
        const int* __restrict__ src, const int* __restrict__ dst,
        const int* __restrict__ snp_ids) {
    int tid = threadIdx.x;
    if (blockIdx.x < SCAT_BLOCKS) {
        int e = blockIdx.x * 256 + tid;
        if (e < NEDGES) {
            int p = atomicAdd(&d_cur[dst[e]], 1);
            d_csr[p] = src[e];
        }
        return;
    }
    int g = (blockIdx.x - SCAT_BLOCKS) * 8 + (tid >> 5);
    int lane = tid & 31;
    int half = lane >> 4, b = lane & 15;
    float a0x=0.f,a0y=0.f,a0z=0.f,a0w=0.f,a1x=0.f,a1y=0.f,a1z=0.f,a1w=0.f;
    int n0 = d_seg[g], n1 = d_seg[g + 1];
    int n = n0 + half;
    for (; n + 2 < n1; n += 4) {
        int i0 = snp_ids[n], i1 = snp_ids[n + 2];
        float s0 = d_snpT[(size_t)i0 * NB + b];
        float s1 = d_snpT[(size_t)i1 * NB + b];
        const float4* p0 = (const float4*)&d_fT[(size_t)i0 * NF];
        const float4* p1 = (const float4*)&d_fT[(size_t)i1 * NF];
        float4 f00 = p0[0], f01 = p0[1];
        float4 f10 = p1[0], f11 = p1[1];
        a0x += s0 * f00.x; a0y += s0 * f00.y; a0z += s0 * f00.z; a0w += s0 * f00.w;
        a1x += s0 * f01.x; a1y += s0 * f01.y; a1z += s0 * f01.z; a1w += s0 * f01.w;
        a0x += s1 * f10.x; a0y += s1 * f10.y; a0z += s1 * f10.z; a0w += s1 * f10.w;
        a1x += s1 * f11.x; a1y += s1 * f11.y; a1z += s1 * f11.z; a1w += s1 * f11.w;
    }
    for (; n < n1; n += 2) {
        int id = snp_ids[n];
        float sv = d_snpT[(size_t)id * NB + b];
        const float4* fp = (const float4*)&d_fT[(size_t)id * NF];
        float4 f0 = fp[0], f1 = fp[1];
        a0x += sv * f0.x; a0y += sv * f0.y; a0z += sv * f0.z; a0w += sv * f0.w;
        a1x += sv * f1.x; a1y += sv * f1.y; a1z += sv * f1.z; a1w += sv * f1.w;
    }
    a0x += __shfl_xor_sync(0xffffffffu, a0x, 16);
    a0y += __shfl_xor_sync(0xffffffffu, a0y, 16);
    a0z += __shfl_xor_sync(0xffffffffu, a0z, 16);
    a0w += __shfl_xor_sync(0xffffffffu, a0w, 16);
    a1x += __shfl_xor_sync(0xffffffffu, a1x, 16);
    a1y += __shfl_xor_sync(0xffffffffu, a1y, 16);
    a1z += __shfl_xor_sync(0xffffffffu, a1z, 16);
    a1w += __shfl_xor_sync(0xffffffffu, a1w, 16);
    if (half == 0) {
        float4* hp = (float4*)&d_hA[((size_t)g * NB + b) * NF];
        hp[0] = make_float4(a0x, a0y, a0z, a0w);
        hp[1] = make_float4(a1x, a1y, a1z, a1w);
    }
}

// ======== cooperative layer core: 1 warp per gene, lane = b*2 + fhalf ========
__device__ __forceinline__ float4 edge_agg32(const float* __restrict__ hin,
                                             int g, int lane, float ep) {
    const float4* h4in = (const float4*)hin;
    float4 a = h4in[(size_t)g * 32 + lane];
    a.x *= ep; a.y *= ep; a.z *= ep; a.w *= ep;
    int e0 = d_off[g], e1 = d_off[g + 1];
    int e = e0;
    for (; e + 4 <= e1; e += 4) {
        int s0 = d_csr[e], s1 = d_csr[e + 1], s2 = d_csr[e + 2], s3 = d_csr[e + 3];
        float4 x0 = h4in[(size_t)s0 * 32 + lane];
        float4 x1 = h4in[(size_t)s1 * 32 + lane];
        float4 x2 = h4in[(size_t)s2 * 32 + lane];
        float4 x3 = h4in[(size_t)s3 * 32 + lane];
        a.x += (x0.x + x1.x) + (x2.x + x3.x);
        a.y += (x0.y + x1.y) + (x2.y + x3.y);
        a.z += (x0.z + x1.z) + (x2.z + x3.z);
        a.w += (x0.w + x1.w) + (x2.w + x3.w);
    }
    for (; e < e1; e++) {
        float4 x = h4in[(size_t)d_csr[e] * 32 + lane];
        a.x += x.x; a.y += x.y; a.z += x.z; a.w += x.w;
    }
    return a;
}

// Cooperative MLP, vectorized weights:
//   sW1t[j*8+f] = W1[f][j]  (transposed, j-major)   -> one LDS.128 per j per lane
//   sW2 [j*8+f] = W2[j][f]  (native row-major)      -> one LDS.128 per j per lane
//   sC1[j] = (g1*BN_RS, b1*g1*BN_RS + bt1)          -> z = gelu(p*Ga + Gb)
//   sC2a/sC2b[f] similar for output BN.
__device__ __forceinline__ float4 gin_mlp32(float4 a, int h4,
                                            const float* sW1t, const float* sW2,
                                            const float2* sC1,
                                            const float* sC2a, const float* sC2b) {
    float o0 = 0.f, o1 = 0.f, o2 = 0.f, o3 = 0.f;
#pragma unroll
    for (int j = 0; j < 16; j++) {
        float4 w1 = *(const float4*)&sW1t[j * 8 + h4];
        float p = a.x * w1.x + a.y * w1.y + a.z * w1.z + a.w * w1.w;
        p += __shfl_xor_sync(0xffffffffu, p, 1);
        float2 c = sC1[j];
        float z = gelu_f(p * c.x + c.y);
        float4 w2 = *(const float4*)&sW2[j * 8 + h4];
        o0 += z * w2.x; o1 += z * w2.y; o2 += z * w2.z; o3 += z * w2.w;
    }
    float4 ca = *(const float4*)&sC2a[h4];
    float4 cb = *(const float4*)&sC2b[h4];
    float4 o;
    o.x = gelu_f(o0 * ca.x + cb.x);
    o.y = gelu_f(o1 * ca.y + cb.y);
    o.z = gelu_f(o2 * ca.z + cb.z);
    o.w = gelu_f(o3 * ca.w + cb.w);
    return o;
}

// -------- launch 4 (PROFILED): GIN layer 0: hA -> hB --------
__global__ void __launch_bounds__(256) k_layer0(
        const float* __restrict__ eps,
        const float* __restrict__ W1, const float* __restrict__ b1,
        const float* __restrict__ g1, const float* __restrict__ bt1,
        const float* __restrict__ W2, const float* __restrict__ b2,
        const float* __restrict__ g2, const float* __restrict__ bt2) {
    __shared__ __align__(16) float sW1t[128], sW2[128];
    __shared__ float2 sC1[16];
    __shared__ __align__(16) float sC2a[8], sC2b[8];
    int tid = threadIdx.x;
    if (tid < 128) {
        sW1t[tid] = W1[(tid & 7) * 16 + (tid >> 3)];   // transpose to j-major
        sW2[tid] = W2[tid];
    }
    if (tid < 16) {
        float ga = g1[tid] * BN_RS;
        sC1[tid] = make_float2(ga, b1[tid] * ga + bt1[tid]);
    }
    if (tid < 8) {
        float ga = g2[tid] * BN_RS;
        sC2a[tid] = ga;
        sC2b[tid] = b2[tid] * ga + bt2[tid];
    }
    __syncthreads();
    int g = blockIdx.x * 8 + (tid >> 5);
    int lane = tid & 31;
    int h4 = (lane & 1) * 4;
    float4 a = edge_agg32(d_hA, g, lane, 1.f + eps[0]);
    float4 o = gin_mlp32(a, h4, sW1t, sW2, sC1, sC2a, sC2b);
    ((float4*)d_hB)[(size_t)g * 32 + lane] = o;
}

// -------- launch 5: GIN layer 1 fused with attentive readout --------
__global__ void __launch_bounds__(256) k_layer1_attn(
        const float* __restrict__ eps,
        const float* __restrict__ W1, const float* __restrict__ b1,
        const float* __restrict__ g1, const float* __restrict__ bt1,
        const float* __restrict__ W2, const float* __restrict__ b2,
        const float* __restrict__ g2, const float* __restrict__ bt2,
        const float* __restrict__ Wk, const float* __restrict__ bk,
        const float* __restrict__ Wq,
        const float* __restrict__ Wv, const float* __restrict__ bv,
        float* __restrict__ w_out) {
    __shared__ __align__(16) float sW1t[128], sW2[128];
    __shared__ float2 sC1[16];
    __shared__ __align__(16) float sC2a[8], sC2b[8];
    __shared__ __align__(16) float sWkT[64], sWvT[64];
    __shared__ float sWq[8], sBk[8], sBv[8];
    __shared__ float red[8][16][8];  // [warp][b][f]
    int tid = threadIdx.x;
    if (tid < 128) {
        sW1t[tid] = W1[128 + (tid & 7) * 16 + (tid >> 3)];
        sW2[tid] = W2[128 + tid];
    }
    if (tid < 16) {
        float ga = g1[16 + tid] * BN_RS;
        sC1[tid] = make_float2(ga, b1[16 + tid] * ga + bt1[16 + tid]);
    }
    if (tid < 8) {
        float ga = g2[8 + tid] * BN_RS;
        sC2a[tid] = ga;
        sC2b[tid] = b2[8 + tid] * ga + bt2[8 + tid];
    }
    if (tid >= 128 && tid < 192) {
        int i = tid - 128;                     // i = j*8 + f
        sWkT[i] = Wk[(i & 7) * 8 + (i >> 3)];  // transpose to j-major
        sWvT[i] = Wv[(i & 7) * 8 + (i >> 3)];
    }
    if (tid >= 192 && tid < 200) {
        int j = tid - 192;
        sWq[j] = Wq[j]; sBk[j] = bk[j]; sBv[j] = bv[j];
    }
    __syncthreads();

    int g = blockIdx.x * 8 + (tid >> 5);
    int lane = tid & 31;
    int fh = lane & 1, b = lane >> 1, h4 = fh * 4;
    float4 a = edge_agg32(d_hB, g, lane, 1.f + eps[1]);
    float4 o = gin_mlp32(a, h4, sW1t, sW2, sC1, sC2a, sC2b);

    // attention: q = key(o) . Wq ; w = sigmoid(q) ; vw = value(o) * w
    float q = 0.f;
#pragma unroll
    for (int j = 0; j < 8; j++) {
        float4 wk = *(const float4*)&sWkT[j * 8 + h4];
        float p = o.x * wk.x + o.y * wk.y + o.z * wk.z + o.w * wk.w;
        p += __shfl_xor_sync(0xffffffffu, p, 1);
        q += (p + sBk[j]) * sWq[j];
    }
    float wv = 1.f / (1.f + expf(-q));
    if (fh == 0) w_out[(size_t)b * NGENES + g] = wv;
    float vw[8];
#pragma unroll
    for (int j = 0; j < 8; j++) {
        float4 wk = *(const float4*)&sWvT[j * 8 + h4];
        float p = o.x * wk.x + o.y * wk.y + o.z * wk.z + o.w * wk.w;
        p += __shfl_xor_sync(0xffffffffu, p, 1);
        vw[j] = (p + sBv[j]) * wv;
    }
    int wid = tid >> 5;
    if (fh == 0) {
#pragma unroll
        for (int j = 0; j < 8; j++) red[wid][b][j] = vw[j];
    }
    __syncthreads();
    if (tid < 128) {
        int bb = tid >> 3, f = tid & 7;
        float s = 0.f;
#pragma unroll
        for (int w = 0; w < 8; w++) s += red[w][bb][f];
        atomicAdd(&d_gh[bb * NF + f], s);
    }
}

// -------- launch 6: final MLP head: 8 -> 64 -> 16 -> 1; re-zero d_gh --------
__global__ void k_head(const float* __restrict__ Wp1, const float* __restrict__ bp1,
                       const float* __restrict__ gp1, const float* __restrict__ btp1,
                       const float* __restrict__ Wp2, const float* __restrict__ bp2,
                       const float* __restrict__ gp2, const float* __restrict__ btp2,
                       const float* __restrict__ Wp3, const float* __restrict__ bp3,
                       float* __restrict__ preds) {
    int b = threadIdx.x;
    if (b < NB) {
        float x[8];
#pragma unroll
        for (int f = 0; f < 8; f++) x[f] = d_gh[b * 8 + f];
        float z1[64];
        for (int j = 0; j < 64; j++) {
            float t = bp1[j];
#pragma unroll
            for (int f = 0; f < 8; f++) t += x[f] * Wp1[f * 64 + j];
            z1[j] = gelu_f(t * BN_RS * gp1[j] + btp1[j]);
        }
        float z2[16];
        for (int k = 0; k < 16; k++) {
            float t = bp2[k];
            for (int j = 0; j < 64; j++) t += z1[j] * Wp2[j * 16 + k];
            z2[k] = gelu_f(t * BN_RS * gp2[k] + btp2[k]);
        }
        float p = bp3[0];
#pragma unroll
        for (int k = 0; k < 16; k++) p += z2[k] * Wp3[k];
        preds[b] = p;
    }
    __syncthreads();
    for (int i = threadIdx.x; i < NB * NF; i += 32) d_gh[i] = 0.f;
}

extern "C" void kernel_launch(void* const* d_in, const int* in_sizes, int n_in,
                              void* d_out, int out_size) {
    const float* snp     = (const float*)d_in[0];
    const int*   snp_ids = (const int*)d_in[1];
    const int*   gon     = (const int*)d_in[2];
    const int*   esrc    = (const int*)d_in[3];
    const int*   edst    = (const int*)d_in[4];
    const float* filters = (const float*)d_in[5];
    const float* eps     = (const float*)d_in[6];
    const float* W1  = (const float*)d_in[7];
    const float* b1  = (const float*)d_in[8];
    const float* g1  = (const float*)d_in[9];
    const float* bt1 = (const float*)d_in[10];
    const float* W2  = (const float*)d_in[11];
    const float* b2  = (const float*)d_in[12];
    const float* g2  = (const float*)d_in[13];
    const float* bt2 = (const float*)d_in[14];
    const float* Wk  = (const float*)d_in[15];
    const float* bk  = (const float*)d_in[16];
    const float* Wq  = (const float*)d_in[17];
    const float* Wv  = (const float*)d_in[18];
    const float* bv  = (const float*)d_in[19];
    const float* Wp1 = (const float*)d_in[20];
    const float* bp1 = (const float*)d_in[21];
    const float* gp1 = (const float*)d_in[22];
    const float* btp1= (const float*)d_in[23];
    const float* Wp2 = (const float*)d_in[24];
    const float* bp2 = (const float*)d_in[25];
    const float* gp2 = (const float*)d_in[26];
    const float* btp2= (const float*)d_in[27];
    const float* Wp3 = (const float*)d_in[28];
    const float* bp3 = (const float*)d_in[29];

    float* out   = (float*)d_out;
    float* preds = out;                               // [16]
    float* outF  = out + NB;                          // [8*500000]
    float* w_out = out + NB + (size_t)NF * NSNPS;     // [16*20000]

    k_hist_seg<<<SCAT_BLOCKS, 256>>>(edst, gon);                                   // 1
    k_scan_pre<<<1 + PRE_BLOCKS, 256>>>(snp, filters, outF);                       // 2
    k_scatter_gene<<<SCAT_BLOCKS + GENE_BLOCKS, 256>>>(esrc, edst, snp_ids);       // 3
    k_layer0<<<GENE_BLOCKS, 256>>>(eps, W1, b1, g1, bt1, W2, b2, g2, bt2);         // 4 <- profiled
    k_layer1_attn<<<GENE_BLOCKS, 256>>>(eps, W1, b1, g1, bt1, W2, b2, g2, bt2,
                                        Wk, bk, Wq, Wv, bv, w_out);                // 5
    k_head<<<1, 32>>>(Wp1, bp1, gp1, btp1, Wp2, bp2, gp2, btp2, Wp3, bp3, preds);  // 6
}

// round 14
// speedup vs baseline: 1.8300x; 1.5524x over previous
#include <cuda_runtime.h>
#include <math.h>

#define NSNPS  500000
#define NGENES 20000
#define NNODES 600000
#define NEDGES 320000
#define NB     16
#define NF     8

#define SCAT_BLOCKS ((NEDGES + 255) / 256)   // 1250
#define PRE_BLOCKS  ((NSNPS + 255) / 256)    // 1954

// rsqrt(1 + 1e-5)
#define BN_RS 0.9999950000374997f

// -------- scratch (static device allocations; zero-initialized at load) --------
__device__ float d_snpT[(size_t)NSNPS * NB];     // 32 MB  [snp][b]
__device__ float d_fT[(size_t)NSNPS * NF];       // 16 MB  [snp][f]
__device__ float d_hA[(size_t)NGENES * NB * NF]; // 10.24 MB [g][b][f]
__device__ float d_hB[(size_t)NGENES * NB * NF];
__device__ int   d_seg[NGENES + 1];
__device__ int   d_deg[NGENES];   // INVARIANT: zero on entry (k_scan re-zeros)
__device__ int   d_cur[NGENES];
__device__ int   d_off[NGENES + 1];
__device__ int   d_csr[NEDGES];
__device__ float d_gh[NB * NF];   // INVARIANT: zero on entry (k_head re-zeros)

// fast exact-form GELU: erff is the fast polynomial path (vs normcdff -> erfcf slow path)
__device__ __forceinline__ float gelu_f(float x) {
    return 0.5f * x * (1.f + erff(x * 0.7071067811865475f));
}

// -------- launch 1: edge-degree histogram + per-gene node-segment starts --------
__global__ void k_hist_seg(const int* __restrict__ dst, const int* __restrict__ gon) {
    int i = blockIdx.x * blockDim.x + threadIdx.x;
    if (i <= NGENES) {
        int lo = 0, hi = NNODES;
        while (lo < hi) {
            int mid = (lo + hi) >> 1;
            if (gon[mid] < i) lo = mid + 1; else hi = mid;
        }
        d_seg[i] = lo;
    }
    if (i < NEDGES) atomicAdd(&d_deg[dst[i]], 1);
}

// -------- launch 2: exclusive scan of deg -> off/cur; re-zero deg --------
__global__ void k_scan() {
    __shared__ int sh[1024];
    const int PER = (NGENES + 1023) / 1024;  // 20
    int tid = threadIdx.x;
    int base = tid * PER;
    int s = 0;
    for (int i = 0; i < PER; i++) {
        int idx = base + i;
        if (idx < NGENES) s += d_deg[idx];
    }
    sh[tid] = s;
    __syncthreads();
    for (int off = 1; off < 1024; off <<= 1) {
        int add = 0;
        if (tid >= off) add = sh[tid - off];
        __syncthreads();
        sh[tid] += add;
        __syncthreads();
    }
    int run = (tid == 0) ? 0 : sh[tid - 1];
    for (int i = 0; i < PER; i++) {
        int idx = base + i;
        if (idx < NGENES) {
            d_off[idx] = run;
            d_cur[idx] = run;
            run += d_deg[idx];
            d_deg[idx] = 0;   // restore invariant for next graph replay
        }
    }
    if (tid == 1023) d_off[NGENES] = run;
}

// -------- launch 3: CSR scatter (blocks 0..1249) + transpose/pre (blocks 1250..) --------
__global__ void __launch_bounds__(256) k_scatter_pre(
        const int* __restrict__ src, const int* __restrict__ dst,
        const float* __restrict__ snp, const float* __restrict__ filters,
        float* __restrict__ outF) {
    __shared__ float smem_s[256][NB + 1];   // +1 pad: conflict-free
    __shared__ float smem_f[256][NF + 1];
    int tid = threadIdx.x;

    if (blockIdx.x < SCAT_BLOCKS) {
        int e = blockIdx.x * 256 + tid;
        if (e < NEDGES) {
            int p = atomicAdd(&d_cur[dst[e]], 1);
            d_csr[p] = src[e];
        }
        return;
    }

    int t0 = (blockIdx.x - SCAT_BLOCKS) * 256;
    int t = t0 + tid;
    bool ok = (t < NSNPS);
#pragma unroll
    for (int b = 0; b < NB; b++)
        smem_s[tid][b] = ok ? snp[(size_t)b * NSNPS + t] : 0.f;
#pragma unroll
    for (int f = 0; f < NF; f++) {
        float w = ok ? filters[(size_t)f * NSNPS + t] : 0.f;
        smem_f[tid][f] = w;
        if (ok) outF[(size_t)f * NSNPS + t] = w;
    }
    __syncthreads();
    if (ok) {
        float4* dp = (float4*)&d_snpT[(size_t)t * NB];
        dp[0] = make_float4(smem_s[tid][0],  smem_s[tid][1],  smem_s[tid][2],  smem_s[tid][3]);
        dp[1] = make_float4(smem_s[tid][4],  smem_s[tid][5],  smem_s[tid][6],  smem_s[tid][7]);
        dp[2] = make_float4(smem_s[tid][8],  smem_s[tid][9],  smem_s[tid][10], smem_s[tid][11]);
        dp[3] = make_float4(smem_s[tid][12], smem_s[tid][13], smem_s[tid][14], smem_s[tid][15]);
        float4* fp = (float4*)&d_fT[(size_t)t * NF];
        fp[0] = make_float4(smem_f[tid][0], smem_f[tid][1], smem_f[tid][2], smem_f[tid][3]);
        fp[1] = make_float4(smem_f[tid][4], smem_f[tid][5], smem_f[tid][6], smem_f[tid][7]);
    }
}

// -------- launch 4 (PROFILED): SNP -> gene readout (16 threads/gene, unroll-4) --------
__global__ void k_gene(const int* __restrict__ snp_ids) {
    int tid = threadIdx.x;
    int g = blockIdx.x * 16 + (tid >> 4);
    int b = tid & 15;
    float4 a0 = make_float4(0.f, 0.f, 0.f, 0.f);
    float4 a1 = a0;
    int n0 = d_seg[g], n1 = d_seg[g + 1];
    int n = n0;
    for (; n + 4 <= n1; n += 4) {
        int i0 = snp_ids[n], i1 = snp_ids[n + 1], i2 = snp_ids[n + 2], i3 = snp_ids[n + 3];
        float s0 = d_snpT[(size_t)i0 * NB + b];
        float s1 = d_snpT[(size_t)i1 * NB + b];
        float s2 = d_snpT[(size_t)i2 * NB + b];
        float s3 = d_snpT[(size_t)i3 * NB + b];
        const float4* p0 = (const float4*)&d_fT[(size_t)i0 * NF];
        const float4* p1 = (const float4*)&d_fT[(size_t)i1 * NF];
        const float4* p2 = (const float4*)&d_fT[(size_t)i2 * NF];
        const float4* p3 = (const float4*)&d_fT[(size_t)i3 * NF];
        float4 f00 = p0[0], f01 = p0[1];
        float4 f10 = p1[0], f11 = p1[1];
        float4 f20 = p2[0], f21 = p2[1];
        float4 f30 = p3[0], f31 = p3[1];
        a0.x += s0 * f00.x; a0.y += s0 * f00.y; a0.z += s0 * f00.z; a0.w += s0 * f00.w;
        a1.x += s0 * f01.x; a1.y += s0 * f01.y; a1.z += s0 * f01.z; a1.w += s0 * f01.w;
        a0.x += s1 * f10.x; a0.y += s1 * f10.y; a0.z += s1 * f10.z; a0.w += s1 * f10.w;
        a1.x += s1 * f11.x; a1.y += s1 * f11.y; a1.z += s1 * f11.z; a1.w += s1 * f11.w;
        a0.x += s2 * f20.x; a0.y += s2 * f20.y; a0.z += s2 * f20.z; a0.w += s2 * f20.w;
        a1.x += s2 * f21.x; a1.y += s2 * f21.y; a1.z += s2 * f21.z; a1.w += s2 * f21.w;
        a0.x += s3 * f30.x; a0.y += s3 * f30.y; a0.z += s3 * f30.z; a0.w += s3 * f30.w;
        a1.x += s3 * f31.x; a1.y += s3 * f31.y; a1.z += s3 * f31.z; a1.w += s3 * f31.w;
    }
    for (; n < n1; n++) {
        int id = snp_ids[n];
        float sv = d_snpT[(size_t)id * NB + b];
        const float4* fp = (const float4*)&d_fT[(size_t)id * NF];
        float4 f0 = fp[0], f1 = fp[1];
        a0.x += sv * f0.x; a0.y += sv * f0.y; a0.z += sv * f0.z; a0.w += sv * f0.w;
        a1.x += sv * f1.x; a1.y += sv * f1.y; a1.z += sv * f1.z; a1.w += sv * f1.w;
    }
    float4* hp = (float4*)&d_hA[((size_t)g * NB + b) * NF];
    hp[0] = a0; hp[1] = a1;
}

// -------- edge aggregation core (16 threads/gene, unroll-2) --------
__device__ __forceinline__ void edge_agg(const float* __restrict__ hin,
                                         int g, int b, float ep,
                                         float4& a0, float4& a1) {
    const float4* hp = (const float4*)&hin[((size_t)g * NB + b) * NF];
    a0 = hp[0]; a1 = hp[1];
    a0.x *= ep; a0.y *= ep; a0.z *= ep; a0.w *= ep;
    a1.x *= ep; a1.y *= ep; a1.z *= ep; a1.w *= ep;
    int e0 = d_off[g], e1 = d_off[g + 1];
    int e = e0;
    for (; e + 2 <= e1; e += 2) {
        int s0 = d_csr[e], s1 = d_csr[e + 1];
        const float4* p0 = (const float4*)&hin[((size_t)s0 * NB + b) * NF];
        const float4* p1 = (const float4*)&hin[((size_t)s1 * NB + b) * NF];
        float4 x00 = p0[0], x01 = p0[1];
        float4 x10 = p1[0], x11 = p1[1];
        a0.x += x00.x + x10.x; a0.y += x00.y + x10.y;
        a0.z += x00.z + x10.z; a0.w += x00.w + x10.w;
        a1.x += x01.x + x11.x; a1.y += x01.y + x11.y;
        a1.z += x01.z + x11.z; a1.w += x01.w + x11.w;
    }
    if (e < e1) {
        int s = d_csr[e];
        const float4* sp = (const float4*)&hin[((size_t)s * NB + b) * NF];
        float4 x0 = sp[0], x1 = sp[1];
        a0.x += x0.x; a0.y += x0.y; a0.z += x0.z; a0.w += x0.w;
        a1.x += x1.x; a1.y += x1.y; a1.z += x1.z; a1.w += x1.w;
    }
}

// -------- GIN MLP(8->16->8)+BN+GELU, vectorized smem weights, folded BN --------
//   sW1t[j*8+f]  = W1[f][j]  (j-major)  -> 2x LDS.128 per j
//   sW2t[f*16+j] = W2[j][f]  (f-major)  -> 4x LDS.128 per f
//   sC1[j] = (g*rs, b*g*rs + bt) ; sC2[f] likewise
__device__ __forceinline__ void gin_mlp(float4 a0, float4 a1, float o[8],
                                        const float* sW1t, const float* sW2t,
                                        const float2* sC1, const float2* sC2) {
    float h2[16];
#pragma unroll
    for (int j = 0; j < 16; j++) {
        float4 wa = *(const float4*)&sW1t[j * 8];
        float4 wb = *(const float4*)&sW1t[j * 8 + 4];
        float t = a0.x * wa.x + a0.y * wa.y + a0.z * wa.z + a0.w * wa.w
                + a1.x * wb.x + a1.y * wb.y + a1.z * wb.z + a1.w * wb.w;
        float2 c = sC1[j];
        h2[j] = gelu_f(t * c.x + c.y);
    }
#pragma unroll
    for (int f = 0; f < 8; f++) {
        const float4* wp = (const float4*)&sW2t[f * 16];
        float4 w0 = wp[0], w1 = wp[1], w2 = wp[2], w3 = wp[3];
        float t = h2[0] * w0.x + h2[1] * w0.y + h2[2] * w0.z + h2[3] * w0.w
                + h2[4] * w1.x + h2[5] * w1.y + h2[6] * w1.z + h2[7] * w1.w
                + h2[8] * w2.x + h2[9] * w2.y + h2[10] * w2.z + h2[11] * w2.w
                + h2[12] * w3.x + h2[13] * w3.y + h2[14] * w3.z + h2[15] * w3.w;
        float2 c = sC2[f];
        o[f] = gelu_f(t * c.x + c.y);
    }
}

// -------- launch 5: GIN layer 0: hA -> hB --------
__global__ void __launch_bounds__(256) k_layer0(
        const float* __restrict__ eps,
        const float* __restrict__ W1, const float* __restrict__ b1,
        const float* __restrict__ g1, const float* __restrict__ bt1,
        const float* __restrict__ W2, const float* __restrict__ b2,
        const float* __restrict__ g2, const float* __restrict__ bt2) {
    __shared__ __align__(16) float sW1t[128], sW2t[128];
    __shared__ float2 sC1[16], sC2[8];
    int tid = threadIdx.x;
    if (tid < 128) {
        sW1t[tid] = W1[(tid & 7) * 16 + (tid >> 3)];    // [j*8+f] <- W1[f][j]
        sW2t[tid] = W2[(tid & 15) * 8 + (tid >> 4)];    // [f*16+j] <- W2[j][f]
    }
    if (tid < 16) {
        float ga = g1[tid] * BN_RS;
        sC1[tid] = make_float2(ga, b1[tid] * ga + bt1[tid]);
    }
    if (tid < 8) {
        float ga = g2[tid] * BN_RS;
        sC2[tid] = make_float2(ga, b2[tid] * ga + bt2[tid]);
    }
    __syncthreads();

    int g = blockIdx.x * 16 + (tid >> 4);
    int b = tid & 15;
    float4 a0, a1;
    edge_agg(d_hA, g, b, 1.f + eps[0], a0, a1);
    float o[8];
    gin_mlp(a0, a1, o, sW1t, sW2t, sC1, sC2);
    float4* op = (float4*)&d_hB[((size_t)g * NB + b) * NF];
    op[0] = make_float4(o[0], o[1], o[2], o[3]);
    op[1] = make_float4(o[4], o[5], o[6], o[7]);
}

// -------- launch 6: GIN layer 1 fused with attentive readout --------
__global__ void __launch_bounds__(256) k_layer1_attn(
        const float* __restrict__ eps,
        const float* __restrict__ W1, const float* __restrict__ b1,
        const float* __restrict__ g1, const float* __restrict__ bt1,
        const float* __restrict__ W2, const float* __restrict__ b2,
        const float* __restrict__ g2, const float* __restrict__ bt2,
        const float* __restrict__ Wk, const float* __restrict__ bk,
        const float* __restrict__ Wq,
        const float* __restrict__ Wv, const float* __restrict__ bv,
        float* __restrict__ w_out) {
    __shared__ __align__(16) float sW1t[128], sW2t[128];
    __shared__ float2 sC1[16], sC2[8];
    __shared__ __align__(16) float sWkT[64], sWvT[64];
    __shared__ float sWq[8], sBk[8], sBv[8];
    __shared__ float red[8][16][8];  // [warp][b][f]
    int tid = threadIdx.x;
    if (tid < 128) {
        sW1t[tid] = W1[128 + (tid & 7) * 16 + (tid >> 3)];
        sW2t[tid] = W2[128 + (tid & 15) * 8 + (tid >> 4)];
    }
    if (tid < 16) {
        float ga = g1[16 + tid] * BN_RS;
        sC1[tid] = make_float2(ga, b1[16 + tid] * ga + bt1[16 + tid]);
    }
    if (tid < 8) {
        float ga = g2[8 + tid] * BN_RS;
        sC2[tid] = make_float2(ga, b2[8 + tid] * ga + bt2[8 + tid]);
    }
    if (tid >= 128 && tid < 192) {
        int i = tid - 128;                     // i = j*8 + f
        sWkT[i] = Wk[(i & 7) * 8 + (i >> 3)];  // j-major
        sWvT[i] = Wv[(i & 7) * 8 + (i >> 3)];
    }
    if (tid >= 192 && tid < 200) {
        int j = tid - 192;
        sWq[j] = Wq[j]; sBk[j] = bk[j]; sBv[j] = bv[j];
    }
    __syncthreads();

    int g = blockIdx.x * 16 + (tid >> 4);
    int b = tid & 15;
    float vw[8];
    {
        float4 a0, a1;
        edge_agg(d_hB, g, b, 1.f + eps[1], a0, a1);
        float o[8];
        gin_mlp(a0, a1, o, sW1t, sW2t, sC1, sC2);
        float4 o0 = make_float4(o[0], o[1], o[2], o[3]);
        float4 o1 = make_float4(o[4], o[5], o[6], o[7]);
        // attention: q = key(o) . Wq ; w = sigmoid(q) ; vw = value(o) * w
        float q = 0.f;
#pragma unroll
        for (int j = 0; j < 8; j++) {
            float4 ka = *(const float4*)&sWkT[j * 8];
            float4 kb = *(const float4*)&sWkT[j * 8 + 4];
            float key = sBk[j]
                + o0.x * ka.x + o0.y * ka.y + o0.z * ka.z + o0.w * ka.w
                + o1.x * kb.x + o1.y * kb.y + o1.z * kb.z + o1.w * kb.w;
            q += key * sWq[j];
        }
        float wv = 1.f / (1.f + expf(-q));
        w_out[(size_t)b * NGENES + g] = wv;
#pragma unroll
        for (int j = 0; j < 8; j++) {
            float4 va = *(const float4*)&sWvT[j * 8];
            float4 vb = *(const float4*)&sWvT[j * 8 + 4];
            float v = sBv[j]
                + o0.x * va.x + o0.y * va.y + o0.z * va.z + o0.w * va.w
                + o1.x * vb.x + o1.y * vb.y + o1.z * vb.z + o1.w * vb.w;
            vw[j] = v * wv;
        }
    }
    // combine the two genes in each warp (lanes 0-15 get lane+16's values)
#pragma unroll
    for (int j = 0; j < 8; j++) vw[j] += __shfl_down_sync(0xffffffffu, vw[j], 16);
    int wid = tid >> 5, lane = tid & 31;
    if (lane < 16) {
#pragma unroll
        for (int j = 0; j < 8; j++) red[wid][lane][j] = vw[j];
    }
    __syncthreads();
    if (tid < 128) {
        int bb = tid >> 3, f = tid & 7;
        float s = 0.f;
#pragma unroll
        for (int w = 0; w < 8; w++) s += red[w][bb][f];
        atomicAdd(&d_gh[bb * NF + f], s);
    }
}

// -------- launch 7: final MLP head: 8 -> 64 -> 16 -> 1; re-zero d_gh --------
__global__ void k_head(const float* __restrict__ Wp1, const float* __restrict__ bp1,
                       const float* __restrict__ gp1, const float* __restrict__ btp1,
                       const float* __restrict__ Wp2, const float* __restrict__ bp2,
                       const float* __restrict__ gp2, const float* __restrict__ btp2,
                       const float* __restrict__ Wp3, const float* __restrict__ bp3,
                       float* __restrict__ preds) {
    int b = threadIdx.x;
    if (b < NB) {
        float x[8];
#pragma unroll
        for (int f = 0; f < 8; f++) x[f] = d_gh[b * 8 + f];
        float z1[64];
        for (int j = 0; j < 64; j++) {
            float t = bp1[j];
#pragma unroll
            for (int f = 0; f < 8; f++) t += x[f] * Wp1[f * 64 + j];
            z1[j] = gelu_f(t * BN_RS * gp1[j] + btp1[j]);
        }
        float z2[16];
        for (int k = 0; k < 16; k++) {
            float t = bp2[k];
            for (int j = 0; j < 64; j++) t += z1[j] * Wp2[j * 16 + k];
            z2[k] = gelu_f(t * BN_RS * gp2[k] + btp2[k]);
        }
        float p = bp3[0];
#pragma unroll
        for (int k = 0; k < 16; k++) p += z2[k] * Wp3[k];
        preds[b] = p;
    }
    __syncthreads();
    // restore invariant: d_gh must be zero for next graph replay
    for (int i = threadIdx.x; i < NB * NF; i += 32) d_gh[i] = 0.f;
}

extern "C" void kernel_launch(void* const* d_in, const int* in_sizes, int n_in,
                              void* d_out, int out_size) {
    const float* snp     = (const float*)d_in[0];
    const int*   snp_ids = (const int*)d_in[1];
    const int*   gon     = (const int*)d_in[2];
    const int*   esrc    = (const int*)d_in[3];
    const int*   edst    = (const int*)d_in[4];
    const float* filters = (const float*)d_in[5];
    const float* eps     = (const float*)d_in[6];
    const float* W1  = (const float*)d_in[7];
    const float* b1  = (const float*)d_in[8];
    const float* g1  = (const float*)d_in[9];
    const float* bt1 = (const float*)d_in[10];
    const float* W2  = (const float*)d_in[11];
    const float* b2  = (const float*)d_in[12];
    const float* g2  = (const float*)d_in[13];
    const float* bt2 = (const float*)d_in[14];
    const float* Wk  = (const float*)d_in[15];
    const float* bk  = (const float*)d_in[16];
    const float* Wq  = (const float*)d_in[17];
    const float* Wv  = (const float*)d_in[18];
    const float* bv  = (const float*)d_in[19];
    const float* Wp1 = (const float*)d_in[20];
    const float* bp1 = (const float*)d_in[21];
    const float* gp1 = (const float*)d_in[22];
    const float* btp1= (const float*)d_in[23];
    const float* Wp2 = (const float*)d_in[24];
    const float* bp2 = (const float*)d_in[25];
    const float* gp2 = (const float*)d_in[26];
    const float* btp2= (const float*)d_in[27];
    const float* Wp3 = (const float*)d_in[28];
    const float* bp3 = (const float*)d_in[29];

    float* out   = (float*)d_out;
    float* preds = out;                               // [16]
    float* outF  = out + NB;                          // [8*500000]
    float* w_out = out + NB + (size_t)NF * NSNPS;     // [16*20000]

    k_hist_seg<<<SCAT_BLOCKS, 256>>>(edst, gon);                                      // 1
    k_scan<<<1, 1024>>>();                                                            // 2
    k_scatter_pre<<<SCAT_BLOCKS + PRE_BLOCKS, 256>>>(esrc, edst, snp, filters, outF); // 3
    k_gene<<<NGENES / 16, 256>>>(snp_ids);                                            // 4 <- profiled
    k_layer0<<<NGENES / 16, 256>>>(eps, W1, b1, g1, bt1, W2, b2, g2, bt2);            // 5
    k_layer1_attn<<<NGENES / 16, 256>>>(eps, W1, b1, g1, bt1, W2, b2, g2, bt2,
                                        Wk, bk, Wq, Wv, bv, w_out);                   // 6
    k_head<<<1, 32>>>(Wp1, bp1, gp1, btp1, Wp2, bp2, gp2, btp2, Wp3, bp3, preds);     // 7
}